// round 13
// baseline (speedup 1.0000x reference)
#include <cuda_runtime.h>
#include <cstdint>
#include <math.h>

// Symmetric Hausdorff distance, B=4, N=M=8192, D=3, fp32.
// Morton-sorted windowed scan + threshold pruning.
//
// 1) Counting-sort both sets by Morton cell id (32^3 grid over [-4,4]^3,
//    outliers clamped -- only ordering, distances stay exact).
// 2) k_seed: exact full mins for 256 strided rows per (dir,batch) -> threshold
//    g_res[b] = max of those mins (atomics on int bits of d^2 >= 0: exact).
// 3) k_main: each row scans a contiguous 512-target window centered at its own
//    Morton position in the opposite (sorted) array -- spatially local, so the
//    window partial ~= true min; one prune check vs g_res[b] kills ~all rows.
//    Survivors do a full pruned scan (every 256) and atomicMax exact mins.
//    The argmax row's partials are always >= answer >= thr (strict < prune),
//    so it is never pruned -> exact; pruning order can only affect rows whose
//    mins are < thr -> output bitwise deterministic.
// 4) k_fin: out[b] = sqrt(g_res[b]).

#define BATCH 4
#define NPB 8192
#define TOT (2*BATCH*NPB)        // 65536
#define G 32
#define GC (G*G*G)               // 32768 cells/grid
#define NCELLS (8*GC)            // 262144
#define RANGE 4.0f
#define INVH 4.0f
#define WIN 512
#define SEEDROWS 256
#define FINF_BITS 0x7f800000

__device__ int    g_cnt[NCELLS];
__device__ int    g_p1[NCELLS];        // within-scan-block exclusive prefix
__device__ int    g_bscan[512];        // scanned block sums
__device__ int    g_cur[NCELLS];
__device__ int    g_cellid[TOT];       // per original point: si*GC + morton
__device__ float4 g_pts4[TOT];         // cell-sorted points
__device__ int    g_seedmin[8*SEEDROWS];
__device__ int    g_res[BATCH];

__device__ __forceinline__ int clampi(int v, int lo, int hi) {
    return v < lo ? lo : (v > hi ? hi : v);
}
__device__ __forceinline__ unsigned part1by2(unsigned x) {
    x = (x | (x << 16)) & 0x030000FFu;
    x = (x | (x << 8))  & 0x0300F00Fu;
    x = (x | (x << 4))  & 0x030C30C3u;
    x = (x | (x << 2))  & 0x09249249u;
    return x;
}
__device__ __forceinline__ int morton_cell(float x, float y, float z) {
    unsigned cx = (unsigned)clampi((int)floorf((x + RANGE) * INVH), 0, G - 1);
    unsigned cy = (unsigned)clampi((int)floorf((y + RANGE) * INVH), 0, G - 1);
    unsigned cz = (unsigned)clampi((int)floorf((z + RANGE) * INVH), 0, G - 1);
    return (int)(part1by2(cx) | (part1by2(cy) << 1) | (part1by2(cz) << 2));
}
__device__ __forceinline__ float3 fetch_pt(const float* __restrict__ pred,
                                           const float* __restrict__ gt, int t) {
    const float* s = (t < BATCH * NPB) ? (pred + 3 * (size_t)t)
                                       : (gt + 3 * (size_t)(t - BATCH * NPB));
    return make_float3(s[0], s[1], s[2]);
}
__device__ __forceinline__ float dist2(const float4 q, const float4 t) {
    float dx = q.x - t.x, dy = q.y - t.y, dz = q.z - t.z;
    return fmaf(dx, dx, fmaf(dy, dy, dz * dz));
}

__global__ void k_zero() {
    int i = blockIdx.x * blockDim.x + threadIdx.x;
    if (i < NCELLS) { g_cnt[i] = 0; g_cur[i] = 0; }
    if (i < 8 * SEEDROWS) g_seedmin[i] = FINF_BITS;
    if (i < BATCH) g_res[i] = 0;
}

__global__ void k_count(const float* __restrict__ pred,
                        const float* __restrict__ gt) {
    int t = blockIdx.x * blockDim.x + threadIdx.x;
    if (t >= TOT) return;
    float3 p = fetch_pt(pred, gt, t);
    int c = (t >> 13) * GC + morton_cell(p.x, p.y, p.z);
    g_cellid[t] = c;
    atomicAdd(&g_cnt[c], 1);
}

__global__ void k_scan1() {
    __shared__ int sh[512];
    const int tid = threadIdx.x;
    const int i = blockIdx.x * 512 + tid;
    int v = g_cnt[i];
    sh[tid] = v; __syncthreads();
    for (int o = 1; o < 512; o <<= 1) {
        int a = (tid >= o) ? sh[tid - o] : 0;
        __syncthreads();
        sh[tid] += a;
        __syncthreads();
    }
    g_p1[i] = sh[tid] - v;
    if (tid == 511) g_bscan[blockIdx.x] = sh[511];
}

__global__ void k_scan2() {
    __shared__ int sh[512];
    const int tid = threadIdx.x;
    int v = g_bscan[tid];
    sh[tid] = v; __syncthreads();
    for (int o = 1; o < 512; o <<= 1) {
        int a = (tid >= o) ? sh[tid - o] : 0;
        __syncthreads();
        sh[tid] += a;
        __syncthreads();
    }
    g_bscan[tid] = sh[tid] - v;
}

__global__ void k_reorder(const float* __restrict__ pred,
                          const float* __restrict__ gt) {
    int t = blockIdx.x * blockDim.x + threadIdx.x;
    if (t >= TOT) return;
    float3 p = fetch_pt(pred, gt, t);
    int c = g_cellid[t];
    int slot = g_p1[c] + g_bscan[c >> 9] + atomicAdd(&g_cur[c], 1);
    g_pts4[slot] = make_float4(p.x, p.y, p.z, 0.0f);
}

// 2048 warps: (db: 8) x (rowgroup: 64) x (target-slice: 4). Exact mins.
__global__ __launch_bounds__(256) void k_seed() {
    const int warp = threadIdx.x >> 5, lane = threadIdx.x & 31;
    const int gw = blockIdx.x * 8 + warp;
    const int ts = gw & 3, rg = (gw >> 2) & 63, db = gw >> 8;
    const int dir = db >> 2, b = db & 3;
    const float4* __restrict__ Q = g_pts4 + (size_t)dir * BATCH * NPB + (size_t)b * NPB;
    const float4* __restrict__ T = g_pts4 + (size_t)(1 - dir) * BATCH * NPB + (size_t)b * NPB;

    float4 q0 = Q[(rg*4+0)*32], q1 = Q[(rg*4+1)*32];
    float4 q2 = Q[(rg*4+2)*32], q3 = Q[(rg*4+3)*32];
    float r0 = __int_as_float(FINF_BITS), r1 = r0, r2 = r0, r3 = r0;
    const int j0 = ts * 2048;
#pragma unroll 2
    for (int j = j0 + lane; j < j0 + 2048; j += 32) {
        const float4 t = T[j];
        r0 = fminf(r0, dist2(q0, t));
        r1 = fminf(r1, dist2(q1, t));
        r2 = fminf(r2, dist2(q2, t));
        r3 = fminf(r3, dist2(q3, t));
    }
    unsigned m0 = __reduce_min_sync(0xffffffffu, (unsigned)__float_as_int(r0));
    unsigned m1 = __reduce_min_sync(0xffffffffu, (unsigned)__float_as_int(r1));
    unsigned m2 = __reduce_min_sync(0xffffffffu, (unsigned)__float_as_int(r2));
    unsigned m3 = __reduce_min_sync(0xffffffffu, (unsigned)__float_as_int(r3));
    if (lane == 0) {
        atomicMin(&g_seedmin[db*SEEDROWS + rg*4+0], (int)m0);
        atomicMin(&g_seedmin[db*SEEDROWS + rg*4+1], (int)m1);
        atomicMin(&g_seedmin[db*SEEDROWS + rg*4+2], (int)m2);
        atomicMin(&g_seedmin[db*SEEDROWS + rg*4+3], (int)m3);
    }
}

__global__ void k_thresh() {
    __shared__ int red[256];
    const int b = blockIdx.x, tid = threadIdx.x;
    int v = max(g_seedmin[b*SEEDROWS + tid], g_seedmin[(b+4)*SEEDROWS + tid]);
    red[tid] = v; __syncthreads();
    for (int s = 128; s > 0; s >>= 1) {
        if (tid < s) red[tid] = max(red[tid], red[tid + s]);
        __syncthreads();
    }
    if (tid == 0) g_res[b] = red[0];
}

// 16384 blocks x 128 thr: warp = one unseeded (sorted) row.
__global__ __launch_bounds__(128) void k_main() {
    const int warp = threadIdx.x >> 5, lane = threadIdx.x & 31;
    const int db = blockIdx.x >> 11;                 // 0..7
    const int n  = (blockIdx.x & 2047) * 4 + warp;   // 0..8191
    if ((n & 31) == 0) return;                       // seeded
    const int dir = db >> 2, b = db & 3;
    const float4* __restrict__ Q = g_pts4 + (size_t)dir * BATCH * NPB + (size_t)b * NPB;
    const float4* __restrict__ T = g_pts4 + (size_t)(1 - dir) * BATCH * NPB + (size_t)b * NPB;

    const float4 q = Q[n];
    // Position of q's cell in the OPPOSITE sorted array -> local window.
    int gb = ((1 - dir) * 4 + b) * GC + morton_cell(q.x, q.y, q.z);
    int pos = g_p1[gb] + g_bscan[gb >> 9];
    int start = clampi(pos - WIN / 2, 0, NPB - WIN);

    const int thr0 = __ldcg(&g_res[b]);              // valid lower bound
    float rmin = __int_as_float(FINF_BITS);
#pragma unroll
    for (int s = 0; s < WIN / 32; s++)               // 16 coalesced LDG.128 steps
        rmin = fminf(rmin, dist2(q, T[start + s * 32 + lane]));
    unsigned wm = __reduce_min_sync(0xffffffffu, (unsigned)__float_as_int(rmin));
    if (__int_as_float((int)wm) < __int_as_float(thr0)) return;  // ~all rows exit

    // Survivor: full pruned scan (window rescanned -- min is idempotent).
    for (int j0 = 0; j0 < NPB; j0 += 256) {
        int thr = __ldcg(&g_res[b]);                 // refresh (stale only under-prunes)
#pragma unroll
        for (int s = 0; s < 8; s++)
            rmin = fminf(rmin, dist2(q, T[j0 + s * 32 + lane]));
        wm = __reduce_min_sync(0xffffffffu, (unsigned)__float_as_int(rmin));
        if (__int_as_float((int)wm) < __int_as_float(thr)) return;
    }
    if (lane == 0) atomicMax(&g_res[b], (int)wm);    // exact completed row min
}

__global__ void k_fin(float* __restrict__ out) {
    const int b = threadIdx.x;
    if (b < BATCH) out[b] = sqrtf(__int_as_float(g_res[b]));
}

extern "C" void kernel_launch(void* const* d_in, const int* in_sizes, int n_in,
                              void* d_out, int out_size) {
    const float* pred = (const float*)d_in[0];
    const float* gt   = (const float*)d_in[1];
    float* out = (float*)d_out;

    k_zero<<<(NCELLS + 255) / 256, 256>>>();
    k_count<<<TOT / 256, 256>>>(pred, gt);
    k_scan1<<<512, 512>>>();
    k_scan2<<<1, 512>>>();
    k_reorder<<<TOT / 256, 256>>>(pred, gt);
    k_seed<<<256, 256>>>();
    k_thresh<<<BATCH, 256>>>();
    k_main<<<16384, 128>>>();
    k_fin<<<1, 32>>>(out);
}

// round 14
// speedup vs baseline: 1.3125x; 1.3125x over previous
#include <cuda_runtime.h>
#include <cstdint>
#include <math.h>

// Symmetric Hausdorff distance, B=4, N=M=8192, D=3, fp32.
// Morton-sorted windowed scan + threshold pruning, 5 launches total
// (launch overhead on this harness is ~4-5us each -- R13's 9-launch version
// lost all algorithmic gains to it).
//
// k_sort:   ONE kernel, 8 blocks (set x batch), 1024 thr: Morton cellid
//           (16^3 grid over [-4,4]^3, h=0.5, outliers clamped -- ordering
//           only, distances stay exact), smem histogram + scan + scatter.
//           Sorted points -> g_pts4, cell starts -> g_cellstart.
// k_seed:   exact full mins for 256 strided (sorted-order) rows per
//           (dir,batch); 2048 warps, 4 rows x 2048-target slices; atomicMin
//           into g_seedmin (int bits of d^2 >= 0: exact, order-free).
// k_thresh: g_res[b] = max over both directions' seeded row mins.
// k_main:   per row: scan a contiguous 512-target window centered at the
//           row's Morton position in the opposite sorted array (spatially
//           local), one prune check vs g_res[b]; survivors (~0.3%) do a full
//           pruned scan. Argmax row's partials >= answer >= thr with strict
//           '<' prune -> never pruned -> exact; every written value is an
//           exact row min -> max is order-independent -> bitwise stable.
// k_fin:    out[b] = sqrt(g_res[b]).

#define BATCH 4
#define NPB 8192
#define TOT (2*BATCH*NPB)        // 65536
#define G 16
#define GC (G*G*G)               // 4096 cells per (set,batch)
#define RANGE 4.0f
#define INVH 2.0f
#define WIN 512
#define SEEDROWS 256
#define FINF_BITS 0x7f800000

__device__ float4 g_pts4[TOT];           // sorted points, [set][batch][slot]
__device__ int    g_cellstart[8*GC];     // exclusive prefix per (set*4+b, cell)
__device__ int    g_seedmin[8*SEEDROWS];
__device__ int    g_res[BATCH];

__device__ __forceinline__ int clampi(int v, int lo, int hi) {
    return v < lo ? lo : (v > hi ? hi : v);
}
__device__ __forceinline__ unsigned part1by2(unsigned x) {
    x = (x | (x << 16)) & 0x030000FFu;
    x = (x | (x << 8))  & 0x0300F00Fu;
    x = (x | (x << 4))  & 0x030C30C3u;
    x = (x | (x << 2))  & 0x09249249u;
    return x;
}
__device__ __forceinline__ int morton_cell(float x, float y, float z) {
    unsigned cx = (unsigned)clampi((int)floorf((x + RANGE) * INVH), 0, G - 1);
    unsigned cy = (unsigned)clampi((int)floorf((y + RANGE) * INVH), 0, G - 1);
    unsigned cz = (unsigned)clampi((int)floorf((z + RANGE) * INVH), 0, G - 1);
    return (int)(part1by2(cx) | (part1by2(cy) << 1) | (part1by2(cz) << 2));
}
__device__ __forceinline__ float dist2(const float4 q, const float4 t) {
    float dx = q.x - t.x, dy = q.y - t.y, dz = q.z - t.z;
    return fmaf(dx, dx, fmaf(dy, dy, dz * dz));
}

// One block per (set,batch): full counting sort in shared memory.
__global__ __launch_bounds__(1024) void k_sort(const float* __restrict__ pred,
                                               const float* __restrict__ gt) {
    __shared__ int hist[GC];      // histogram, then reused as scatter cursors
    __shared__ int scanb[GC];     // exclusive prefix
    __shared__ int aux[1024];

    const int si  = blockIdx.x;                    // set*4 + batch
    const int tid = threadIdx.x;
    const float* __restrict__ src =
        (si < 4) ? (pred + (size_t)si * NPB * 3)
                 : (gt + (size_t)(si - 4) * NPB * 3);

    for (int c = tid; c < GC; c += 1024) hist[c] = 0;
    if (tid < SEEDROWS) g_seedmin[si * SEEDROWS + tid] = FINF_BITS;
    __syncthreads();

    float4 p[8]; int cid[8];
#pragma unroll
    for (int k = 0; k < 8; k++) {
        const int i = tid + k * 1024;
        const float* s = src + 3 * (size_t)i;
        p[k] = make_float4(s[0], s[1], s[2], 0.0f);
        cid[k] = morton_cell(p[k].x, p[k].y, p[k].z);
        atomicAdd(&hist[cid[k]], 1);
    }
    __syncthreads();

    // Exclusive scan of 4096 counts: 4 per thread + Hillis-Steele over 1024 sums.
    const int base = tid * 4;
    int h0 = hist[base], h1 = hist[base+1], h2 = hist[base+2], h3 = hist[base+3];
    int ts = h0 + h1 + h2 + h3;
    aux[tid] = ts; __syncthreads();
    for (int o = 1; o < 1024; o <<= 1) {
        int a = (tid >= o) ? aux[tid - o] : 0;
        __syncthreads();
        aux[tid] += a;
        __syncthreads();
    }
    int off = aux[tid] - ts;                       // exclusive thread offset
    scanb[base]     = off;
    scanb[base + 1] = off + h0;
    scanb[base + 2] = off + h0 + h1;
    scanb[base + 3] = off + h0 + h1 + h2;
    g_cellstart[si * GC + base]     = scanb[base];
    g_cellstart[si * GC + base + 1] = scanb[base + 1];
    g_cellstart[si * GC + base + 2] = scanb[base + 2];
    g_cellstart[si * GC + base + 3] = scanb[base + 3];
    hist[base] = 0; hist[base+1] = 0; hist[base+2] = 0; hist[base+3] = 0;
    __syncthreads();

#pragma unroll
    for (int k = 0; k < 8; k++) {
        int slot = scanb[cid[k]] + atomicAdd(&hist[cid[k]], 1);
        g_pts4[si * NPB + slot] = p[k];
    }
}

// 2048 warps: (db: 8) x (rowgroup: 64) x (target-slice: 4). Exact row mins.
__global__ __launch_bounds__(256) void k_seed() {
    const int warp = threadIdx.x >> 5, lane = threadIdx.x & 31;
    const int gw = blockIdx.x * 8 + warp;
    const int ts = gw & 3, rg = (gw >> 2) & 63, db = gw >> 8;
    const int dir = db >> 2, b = db & 3;
    const float4* __restrict__ Q = g_pts4 + (size_t)dir * BATCH * NPB + (size_t)b * NPB;
    const float4* __restrict__ T = g_pts4 + (size_t)(1 - dir) * BATCH * NPB + (size_t)b * NPB;

    float4 q0 = Q[(rg*4+0)*32], q1 = Q[(rg*4+1)*32];
    float4 q2 = Q[(rg*4+2)*32], q3 = Q[(rg*4+3)*32];
    float r0 = __int_as_float(FINF_BITS), r1 = r0, r2 = r0, r3 = r0;
    const int j0 = ts * 2048;
#pragma unroll 2
    for (int j = j0 + lane; j < j0 + 2048; j += 32) {
        const float4 t = T[j];                     // one LDG.128, 4 queries
        r0 = fminf(r0, dist2(q0, t));
        r1 = fminf(r1, dist2(q1, t));
        r2 = fminf(r2, dist2(q2, t));
        r3 = fminf(r3, dist2(q3, t));
    }
    unsigned m0 = __reduce_min_sync(0xffffffffu, (unsigned)__float_as_int(r0));
    unsigned m1 = __reduce_min_sync(0xffffffffu, (unsigned)__float_as_int(r1));
    unsigned m2 = __reduce_min_sync(0xffffffffu, (unsigned)__float_as_int(r2));
    unsigned m3 = __reduce_min_sync(0xffffffffu, (unsigned)__float_as_int(r3));
    if (lane == 0) {
        atomicMin(&g_seedmin[db*SEEDROWS + rg*4+0], (int)m0);
        atomicMin(&g_seedmin[db*SEEDROWS + rg*4+1], (int)m1);
        atomicMin(&g_seedmin[db*SEEDROWS + rg*4+2], (int)m2);
        atomicMin(&g_seedmin[db*SEEDROWS + rg*4+3], (int)m3);
    }
}

__global__ void k_thresh() {
    __shared__ int red[256];
    const int b = blockIdx.x, tid = threadIdx.x;
    int v = max(g_seedmin[b*SEEDROWS + tid], g_seedmin[(b+4)*SEEDROWS + tid]);
    red[tid] = v; __syncthreads();
    for (int s = 128; s > 0; s >>= 1) {
        if (tid < s) red[tid] = max(red[tid], red[tid + s]);
        __syncthreads();
    }
    if (tid == 0) g_res[b] = red[0];               // plain store (pre-main)
}

// 16384 blocks x 128 thr: warp = one unseeded (sorted) row.
__global__ __launch_bounds__(128) void k_main() {
    const int warp = threadIdx.x >> 5, lane = threadIdx.x & 31;
    const int db = blockIdx.x >> 11;                 // 0..7
    const int n  = (blockIdx.x & 2047) * 4 + warp;   // 0..8191
    if ((n & 31) == 0) return;                       // seeded
    const int dir = db >> 2, b = db & 3;
    const float4* __restrict__ Q = g_pts4 + (size_t)dir * BATCH * NPB + (size_t)b * NPB;
    const float4* __restrict__ T = g_pts4 + (size_t)(1 - dir) * BATCH * NPB + (size_t)b * NPB;

    const float4 q = Q[n];
    // Window centered at q's cell position in the opposite sorted array.
    int pos = g_cellstart[((1 - dir) * 4 + b) * GC + morton_cell(q.x, q.y, q.z)];
    int start = clampi(pos - WIN / 2, 0, NPB - WIN);

    const int thr0 = __ldcg(&g_res[b]);              // valid lower bound
    float rmin = __int_as_float(FINF_BITS);
#pragma unroll
    for (int s = 0; s < WIN / 32; s++)               // 16 coalesced LDG.128 steps
        rmin = fminf(rmin, dist2(q, T[start + s * 32 + lane]));
    unsigned wm = __reduce_min_sync(0xffffffffu, (unsigned)__float_as_int(rmin));
    if (__int_as_float((int)wm) < __int_as_float(thr0)) return;  // ~all rows exit

    // Survivor: full pruned scan (window rescan is idempotent under min).
    for (int j0 = 0; j0 < NPB; j0 += 256) {
        int thr = __ldcg(&g_res[b]);                 // stale only under-prunes
#pragma unroll
        for (int s = 0; s < 8; s++)
            rmin = fminf(rmin, dist2(q, T[j0 + s * 32 + lane]));
        wm = __reduce_min_sync(0xffffffffu, (unsigned)__float_as_int(rmin));
        if (__int_as_float((int)wm) < __int_as_float(thr)) return;
    }
    if (lane == 0) atomicMax(&g_res[b], (int)wm);    // exact completed row min
}

__global__ void k_fin(float* __restrict__ out) {
    const int b = threadIdx.x;
    if (b < BATCH) out[b] = sqrtf(__int_as_float(g_res[b]));
}

extern "C" void kernel_launch(void* const* d_in, const int* in_sizes, int n_in,
                              void* d_out, int out_size) {
    const float* pred = (const float*)d_in[0];
    const float* gt   = (const float*)d_in[1];
    float* out = (float*)d_out;

    k_sort<<<8, 1024>>>(pred, gt);
    k_seed<<<256, 256>>>();
    k_thresh<<<BATCH, 256>>>();
    k_main<<<16384, 128>>>();
    k_fin<<<1, 32>>>(out);
}